// round 9
// baseline (speedup 1.0000x reference)
#include <cuda_runtime.h>

#define B_    64
#define CIN   512
#define COUT  512
#define HW    784      // 28*28
#define FAN   513      // CIN + 1 (rate column)
#define KSEL  256      // K = COUT * 0.5
#define RATE  0.5f

// Scratch (allocation-free rule: __device__ globals)
__device__ float d_s_scr[B_ * CIN];    // per-(b,c) mean |x|
__device__ float d_g_scr[B_ * COUT];   // gate values after relu

// ---------------------------------------------------------------------------
// Kernel 1: s[b,c] = mean(|x[b,c,:,:]|). EXACT best-measured config (R1:
// 18.59us, 72.2% DRAM): 4096 blocks x 256 thr, one warp per row, NO
// __launch_bounds__ (ptxas picks 36 regs -> max load batching), plain LDG
// (no __ldcs: measured -0.9us). Only addition: end-of-kernel PDL trigger.
// ---------------------------------------------------------------------------
__global__ void k1_absmean(const float* __restrict__ x) {
    int row  = blockIdx.x * 8 + (threadIdx.x >> 5);   // 32768 rows
    int lane = threadIdx.x & 31;
    const float4* p = reinterpret_cast<const float4*>(x) + (size_t)row * 196;
    float acc = 0.f;
    #pragma unroll
    for (int i = 0; i < 7; i++) {                      // 196 float4 per row
        int idx = lane + i * 32;
        if (idx < 196) {
            float4 v = p[idx];
            acc += fabsf(v.x) + fabsf(v.y) + fabsf(v.z) + fabsf(v.w);
        }
    }
    #pragma unroll
    for (int o = 16; o; o >>= 1) acc += __shfl_xor_sync(0xffffffffu, acc, o);
    if (lane == 0) d_s_scr[row] = acc * (1.0f / (float)HW);
    cudaTriggerProgrammaticLaunchCompletion();
}

// ---------------------------------------------------------------------------
// Kernel 2: g[b,c] = relu(dot(s_ext[b,:], W[c,:]) + bias[c])
// Grid (16,8): block = 4 batches x 64 channels. PDL: stage this block's W
// tile (64x513 floats = 131KB) into dynamic smem BEFORE the grid-dependency
// sync (overlaps k1's drain), then sync, load s, compute from smem.
// ---------------------------------------------------------------------------
#define W_TILE_FLOATS (64 * FAN)            // 32832, divisible by 4
#define S_STRIDE      520
#define K2_SMEM_BYTES ((W_TILE_FLOATS + 4 * S_STRIDE) * 4)

extern __shared__ float k2_smem[];

__global__ void k2_gate(const float* __restrict__ W, const float* __restrict__ bias) {
    float* W_sm = k2_smem;                       // [64][513] flat
    float* s_sm = k2_smem + W_TILE_FLOATS;       // [4][520]
    int tid = threadIdx.x;
    int b0  = blockIdx.x * 4;
    int c0  = blockIdx.y * 64;

    // ---- prologue (independent of k1): stage W tile as float4 ----
    {
        const float4* wsrc = reinterpret_cast<const float4*>(W + (size_t)c0 * FAN);
        float4* wdst = reinterpret_cast<float4*>(W_sm);
        #pragma unroll 4
        for (int i = tid; i < W_TILE_FLOATS / 4; i += 512) wdst[i] = wsrc[i];
    }

    // ---- wait for k1's stores to be visible ----
    cudaGridDependencySynchronize();

    for (int idx = tid; idx < 4 * FAN; idx += 512) {
        int bb = idx / FAN, k = idx - bb * FAN;
        s_sm[bb * S_STRIDE + k] = (k < CIN) ? d_s_scr[(b0 + bb) * CIN + k] : RATE;
    }
    __syncthreads();

    int warp = tid >> 5, lane = tid & 31;
    int cl = warp * 4;                       // channel offset within tile
    float acc[4][4];
    #pragma unroll
    for (int bb = 0; bb < 4; bb++)
        #pragma unroll
        for (int cc = 0; cc < 4; cc++) acc[bb][cc] = 0.f;

    #pragma unroll 4
    for (int k = lane; k < FAN; k += 32) {
        float wv[4], sv[4];
        #pragma unroll
        for (int cc = 0; cc < 4; cc++) wv[cc] = W_sm[(cl + cc) * FAN + k];
        #pragma unroll
        for (int bb = 0; bb < 4; bb++) sv[bb] = s_sm[bb * S_STRIDE + k];
        #pragma unroll
        for (int bb = 0; bb < 4; bb++)
            #pragma unroll
            for (int cc = 0; cc < 4; cc++) acc[bb][cc] += wv[cc] * sv[bb];
    }
    #pragma unroll
    for (int o = 16; o; o >>= 1)
        #pragma unroll
        for (int bb = 0; bb < 4; bb++)
            #pragma unroll
            for (int cc = 0; cc < 4; cc++)
                acc[bb][cc] += __shfl_xor_sync(0xffffffffu, acc[bb][cc], o);

    if (lane == 0) {
        #pragma unroll
        for (int cc = 0; cc < 4; cc++) {
            float bv = bias[c0 + cl + cc];
            #pragma unroll
            for (int bb = 0; bb < 4; bb++)
                d_g_scr[(b0 + bb) * COUT + c0 + cl + cc] = fmaxf(acc[bb][cc] + bv, 0.f);
        }
    }
    cudaTriggerProgrammaticLaunchCompletion();
}

// ---------------------------------------------------------------------------
// Kernel 3: zero the KSEL smallest per row (radix-select, 4 byte passes),
// renormalize to sum = COUT. PDL: hist-zero before the grid sync.
// ---------------------------------------------------------------------------
__global__ void k3_select(float* __restrict__ out) {
    __shared__ unsigned hist[256];
    __shared__ unsigned sh_digit, sh_cumbefore;
    __shared__ unsigned wcnt[16];
    __shared__ float ssum[17];

    int b = blockIdx.x;
    int c = threadIdx.x;
    int warp = c >> 5, lane = c & 31;

    if (c < 256) hist[c] = 0;                // overlap-able prologue

    cudaGridDependencySynchronize();

    float gc = d_g_scr[b * COUT + c];
    unsigned key = __float_as_uint(gc);      // gc >= 0 -> monotone

    unsigned prefix = 0, mask = 0;
    unsigned target = KSEL - 1;              // remaining rank in candidate set
    unsigned countless = 0;                  // # keys strictly < tau (global)

    #pragma unroll
    for (int shift = 24; shift >= 0; shift -= 8) {
        if (shift != 24 && c < 256) hist[c] = 0;
        __syncthreads();
        bool active = ((key & mask) == prefix);
        if (active) atomicAdd(&hist[(key >> shift) & 255u], 1u);
        __syncthreads();

        if (c < 32) {   // warp0: find digit containing 'target'
            unsigned s = 0;
            #pragma unroll
            for (int k = 0; k < 8; k++) s += hist[lane * 8 + k];
            unsigned incl = s;
            #pragma unroll
            for (int o = 1; o < 32; o <<= 1) {
                unsigned t = __shfl_up_sync(0xffffffffu, incl, o);
                if (lane >= o) incl += t;
            }
            unsigned excl = incl - s;
            if (excl <= target && target < incl) {
                unsigned cum = excl;
                unsigned d = lane * 8;
                #pragma unroll
                for (int k = 0; k < 8; k++) {
                    unsigned h = hist[lane * 8 + k];
                    if (cum + h > target) { d = lane * 8 + k; break; }
                    cum += h;
                }
                sh_digit = d;
                sh_cumbefore = cum;
            }
        }
        __syncthreads();
        unsigned cb = sh_cumbefore;
        unsigned dg = sh_digit;
        target    -= cb;
        countless += cb;
        prefix |= dg << shift;
        mask   |= 0xFFu << shift;
        __syncthreads();
    }

    unsigned tau = prefix;
    unsigned E = KSEL - countless;           // # tau-equal elements to zero
    bool eq = (key == tau);

    unsigned ball = __ballot_sync(0xffffffffu, eq);
    if (lane == 0) wcnt[warp] = __popc(ball);
    __syncthreads();
    unsigned woff = 0;
    #pragma unroll
    for (int w = 0; w < 16; w++) woff += (w < warp) ? wcnt[w] : 0u;
    unsigned myoff = woff + __popc(ball & ((1u << lane) - 1u));

    bool zero = (key < tau) || (eq && myoff < E);
    float t = zero ? 0.f : gc;

    float sum = t;
    #pragma unroll
    for (int o = 16; o; o >>= 1) sum += __shfl_xor_sync(0xffffffffu, sum, o);
    if (lane == 0) ssum[warp] = sum;
    __syncthreads();
    if (c == 0) {
        float tot = 0.f;
        #pragma unroll
        for (int w = 0; w < 16; w++) tot += ssum[w];
        ssum[16] = tot;
    }
    __syncthreads();
    out[b * COUT + c] = t * ((float)COUT / ssum[16]);
}

// ---------------------------------------------------------------------------
extern "C" void kernel_launch(void* const* d_in, const int* in_sizes, int n_in,
                              void* d_out, int out_size) {
    const float* x    = (const float*)d_in[0];
    const float* W    = (const float*)d_in[1];
    const float* bias = (const float*)d_in[2];
    float* out = (float*)d_out;

    cudaFuncSetAttribute(k2_gate, cudaFuncAttributeMaxDynamicSharedMemorySize,
                         K2_SMEM_BYTES);

    k1_absmean<<<4096, 256>>>(x);

    // k2 with Programmatic Dependent Launch (launches into k1's drain window)
    {
        cudaLaunchConfig_t cfg = {};
        cfg.gridDim  = dim3(16, 8);
        cfg.blockDim = dim3(512);
        cfg.dynamicSmemBytes = K2_SMEM_BYTES;
        cfg.stream = 0;
        cudaLaunchAttribute at[1];
        at[0].id = cudaLaunchAttributeProgrammaticStreamSerialization;
        at[0].val.programmaticStreamSerializationAllowed = 1;
        cfg.attrs = at;
        cfg.numAttrs = 1;
        cudaLaunchKernelEx(&cfg, k2_gate, W, bias);
    }

    // k3 with PDL: dispatch overlaps k2's tail.
    {
        cudaLaunchConfig_t cfg = {};
        cfg.gridDim  = dim3(B_);
        cfg.blockDim = dim3(512);
        cfg.dynamicSmemBytes = 0;
        cfg.stream = 0;
        cudaLaunchAttribute at[1];
        at[0].id = cudaLaunchAttributeProgrammaticStreamSerialization;
        at[0].val.programmaticStreamSerializationAllowed = 1;
        cfg.attrs = at;
        cfg.numAttrs = 1;
        cudaLaunchKernelEx(&cfg, k3_select, out);
    }
}

// round 10
// speedup vs baseline: 1.1122x; 1.1122x over previous
#include <cuda_runtime.h>
#include <cstdint>

#define B_    64
#define CIN   512
#define COUT  512
#define HW    784      // 28*28
#define FAN   513      // CIN + 1 (rate column)
#define KSEL  256      // K = COUT * 0.5
#define RATE  0.5f

#define NROWS      (B_ * CIN)          // 32768
#define TILE_ROWS  8
#define TILE_FLTS  (TILE_ROWS * HW)    // 6272 floats
#define TILE_BYTES (TILE_FLTS * 4)     // 25088 bytes (16B-multiple)
#define NTILES     (NROWS / TILE_ROWS) // 4096
#define K1_BLOCKS  592                 // 148 x 4 -> single co-resident wave
#define K1_SMEM    (2 * TILE_BYTES + 32)

// Scratch (allocation-free rule: __device__ globals)
__device__ float d_s_scr[B_ * CIN];    // per-(b,c) mean |x|
__device__ float d_g_scr[B_ * COUT];   // gate values after relu

// ---- mbarrier / bulk-async helpers -----------------------------------------
__device__ __forceinline__ uint32_t smem_u32(const void* p) {
    uint32_t a;
    asm("{ .reg .u64 t; cvta.to.shared.u64 t, %1; cvt.u32.u64 %0, t; }"
        : "=r"(a) : "l"(p));
    return a;
}
__device__ __forceinline__ void mbar_init(uint32_t mbar, uint32_t cnt) {
    asm volatile("mbarrier.init.shared.b64 [%0], %1;" :: "r"(mbar), "r"(cnt) : "memory");
}
__device__ __forceinline__ void mbar_expect_tx(uint32_t mbar, uint32_t bytes) {
    asm volatile("mbarrier.arrive.expect_tx.shared.b64 _, [%0], %1;"
                 :: "r"(mbar), "r"(bytes) : "memory");
}
__device__ __forceinline__ void mbar_wait(uint32_t mbar, uint32_t phase) {
    asm volatile(
        "{\n\t.reg .pred P;\n"
        "W_%=:\n\t"
        "mbarrier.try_wait.parity.acquire.cta.shared::cta.b64 P, [%0], %1, 0x989680;\n\t"
        "@P bra.uni D_%=;\n\t"
        "bra.uni W_%=;\n"
        "D_%=:\n\t}"
        :: "r"(mbar), "r"(phase) : "memory");
}
__device__ __forceinline__ void bulk_g2s(uint32_t dst_smem, const void* src_gmem,
                                         uint32_t bytes, uint32_t mbar) {
    asm volatile(
        "{ .reg .u64 g; cvta.to.global.u64 g, %1;\n\t"
        "cp.async.bulk.shared::cluster.global.mbarrier::complete_tx::bytes "
        "[%0], [g], %2, [%3]; }"
        :: "r"(dst_smem), "l"(src_gmem), "r"(bytes), "r"(mbar) : "memory");
}
__device__ __forceinline__ void fence_async_proxy() {
    asm volatile("fence.proxy.async.shared::cta;" ::: "memory");
}

// ---------------------------------------------------------------------------
// Kernel 1: s[b,c] = mean(|x[b,c,:,:]|).
// Bulk-async (TMA-path) streaming: persistent 592-block single wave, each
// block walks 8-row (25KB) tiles with double-buffered cp.async.bulk into
// smem, warp-per-row LDS.128 reduction. Bypasses the LDG issue/queue path
// that plateaued at 5.4-5.7 TB/s across 8 configs. PDL trigger at end.
// ---------------------------------------------------------------------------
__global__ void __launch_bounds__(256) k1_absmean(const float* __restrict__ x) {
    extern __shared__ char smem[];
    float* bufp[2] = { reinterpret_cast<float*>(smem),
                       reinterpret_cast<float*>(smem + TILE_BYTES) };
    uint32_t buf_s[2] = { smem_u32(smem), smem_u32(smem + TILE_BYTES) };
    uint32_t mb[2]    = { smem_u32(smem + 2 * TILE_BYTES),
                          smem_u32(smem + 2 * TILE_BYTES + 16) };

    int tid  = threadIdx.x;
    int warp = tid >> 5, lane = tid & 31;

    if (tid == 0) { mbar_init(mb[0], 1); mbar_init(mb[1], 1); }
    __syncthreads();

    // prologue: issue first two tiles
    if (tid == 0) {
        int t0 = blockIdx.x;
        mbar_expect_tx(mb[0], TILE_BYTES);
        bulk_g2s(buf_s[0], x + (size_t)t0 * TILE_FLTS, TILE_BYTES, mb[0]);
        int t1 = t0 + K1_BLOCKS;
        if (t1 < NTILES) {
            mbar_expect_tx(mb[1], TILE_BYTES);
            bulk_g2s(buf_s[1], x + (size_t)t1 * TILE_FLTS, TILE_BYTES, mb[1]);
        }
    }

    uint32_t phase[2] = {0, 0};
    int bi = 0;
    for (int t = blockIdx.x; t < NTILES; t += K1_BLOCKS) {
        mbar_wait(mb[bi], phase[bi]);
        phase[bi] ^= 1;

        // warp w reduces row w of this tile (196 float4 from smem)
        const float4* rp = reinterpret_cast<const float4*>(bufp[bi]) + warp * 196;
        float acc = 0.f;
        #pragma unroll
        for (int i = 0; i < 7; i++) {
            int idx = lane + i * 32;
            if (idx < 196) {
                float4 v = rp[idx];
                acc += fabsf(v.x) + fabsf(v.y) + fabsf(v.z) + fabsf(v.w);
            }
        }
        #pragma unroll
        for (int o = 16; o; o >>= 1) acc += __shfl_xor_sync(0xffffffffu, acc, o);
        if (lane == 0) d_s_scr[t * TILE_ROWS + warp] = acc * (1.0f / (float)HW);

        __syncthreads();                       // all warps done reading buf bi
        if (tid == 0) {
            int tn = t + 2 * K1_BLOCKS;
            if (tn < NTILES) {
                fence_async_proxy();           // order smem reads before overwrite
                mbar_expect_tx(mb[bi], TILE_BYTES);
                bulk_g2s(buf_s[bi], x + (size_t)tn * TILE_FLTS, TILE_BYTES, mb[bi]);
            }
        }
        bi ^= 1;
    }
    cudaTriggerProgrammaticLaunchCompletion();
}

// ---------------------------------------------------------------------------
// Kernel 2: g[b,c] = relu(dot(s_ext[b,:], W[c,:]) + bias[c])
// Grid (16,8): block = 4 batches x 64 channels. PDL: stage this block's W
// tile (131KB) into dynamic smem BEFORE the grid-dependency sync (overlaps
// k1's drain), then sync, load s, compute from smem.
// ---------------------------------------------------------------------------
#define W_TILE_FLOATS (64 * FAN)            // 32832
#define S_STRIDE      520
#define K2_SMEM_BYTES ((W_TILE_FLOATS + 4 * S_STRIDE) * 4)

extern __shared__ float k2_smem[];

__global__ void k2_gate(const float* __restrict__ W, const float* __restrict__ bias) {
    float* W_sm = k2_smem;                       // [64][513] flat
    float* s_sm = k2_smem + W_TILE_FLOATS;       // [4][520]
    int tid = threadIdx.x;
    int b0  = blockIdx.x * 4;
    int c0  = blockIdx.y * 64;

    {
        const float4* wsrc = reinterpret_cast<const float4*>(W + (size_t)c0 * FAN);
        float4* wdst = reinterpret_cast<float4*>(W_sm);
        #pragma unroll 4
        for (int i = tid; i < W_TILE_FLOATS / 4; i += 512) wdst[i] = wsrc[i];
    }

    cudaGridDependencySynchronize();

    for (int idx = tid; idx < 4 * FAN; idx += 512) {
        int bb = idx / FAN, k = idx - bb * FAN;
        s_sm[bb * S_STRIDE + k] = (k < CIN) ? d_s_scr[(b0 + bb) * CIN + k] : RATE;
    }
    __syncthreads();

    int warp = tid >> 5, lane = tid & 31;
    int cl = warp * 4;
    float acc[4][4];
    #pragma unroll
    for (int bb = 0; bb < 4; bb++)
        #pragma unroll
        for (int cc = 0; cc < 4; cc++) acc[bb][cc] = 0.f;

    #pragma unroll 4
    for (int k = lane; k < FAN; k += 32) {
        float wv[4], sv[4];
        #pragma unroll
        for (int cc = 0; cc < 4; cc++) wv[cc] = W_sm[(cl + cc) * FAN + k];
        #pragma unroll
        for (int bb = 0; bb < 4; bb++) sv[bb] = s_sm[bb * S_STRIDE + k];
        #pragma unroll
        for (int bb = 0; bb < 4; bb++)
            #pragma unroll
            for (int cc = 0; cc < 4; cc++) acc[bb][cc] += wv[cc] * sv[bb];
    }
    #pragma unroll
    for (int o = 16; o; o >>= 1)
        #pragma unroll
        for (int bb = 0; bb < 4; bb++)
            #pragma unroll
            for (int cc = 0; cc < 4; cc++)
                acc[bb][cc] += __shfl_xor_sync(0xffffffffu, acc[bb][cc], o);

    if (lane == 0) {
        #pragma unroll
        for (int cc = 0; cc < 4; cc++) {
            float bv = bias[c0 + cl + cc];
            #pragma unroll
            for (int bb = 0; bb < 4; bb++)
                d_g_scr[(b0 + bb) * COUT + c0 + cl + cc] = fmaxf(acc[bb][cc] + bv, 0.f);
        }
    }
    cudaTriggerProgrammaticLaunchCompletion();
}

// ---------------------------------------------------------------------------
// Kernel 3: zero the KSEL smallest per row (radix-select, 4 byte passes),
// renormalize to sum = COUT. PDL: hist-zero before the grid sync.
// ---------------------------------------------------------------------------
__global__ void k3_select(float* __restrict__ out) {
    __shared__ unsigned hist[256];
    __shared__ unsigned sh_digit, sh_cumbefore;
    __shared__ unsigned wcnt[16];
    __shared__ float ssum[17];

    int b = blockIdx.x;
    int c = threadIdx.x;
    int warp = c >> 5, lane = c & 31;

    if (c < 256) hist[c] = 0;

    cudaGridDependencySynchronize();

    float gc = d_g_scr[b * COUT + c];
    unsigned key = __float_as_uint(gc);

    unsigned prefix = 0, mask = 0;
    unsigned target = KSEL - 1;
    unsigned countless = 0;

    #pragma unroll
    for (int shift = 24; shift >= 0; shift -= 8) {
        if (shift != 24 && c < 256) hist[c] = 0;
        __syncthreads();
        bool active = ((key & mask) == prefix);
        if (active) atomicAdd(&hist[(key >> shift) & 255u], 1u);
        __syncthreads();

        if (c < 32) {
            unsigned s = 0;
            #pragma unroll
            for (int k = 0; k < 8; k++) s += hist[lane * 8 + k];
            unsigned incl = s;
            #pragma unroll
            for (int o = 1; o < 32; o <<= 1) {
                unsigned t = __shfl_up_sync(0xffffffffu, incl, o);
                if (lane >= o) incl += t;
            }
            unsigned excl = incl - s;
            if (excl <= target && target < incl) {
                unsigned cum = excl;
                unsigned d = lane * 8;
                #pragma unroll
                for (int k = 0; k < 8; k++) {
                    unsigned h = hist[lane * 8 + k];
                    if (cum + h > target) { d = lane * 8 + k; break; }
                    cum += h;
                }
                sh_digit = d;
                sh_cumbefore = cum;
            }
        }
        __syncthreads();
        unsigned cb = sh_cumbefore;
        unsigned dg = sh_digit;
        target    -= cb;
        countless += cb;
        prefix |= dg << shift;
        mask   |= 0xFFu << shift;
        __syncthreads();
    }

    unsigned tau = prefix;
    unsigned E = KSEL - countless;
    bool eq = (key == tau);

    unsigned ball = __ballot_sync(0xffffffffu, eq);
    if (lane == 0) wcnt[warp] = __popc(ball);
    __syncthreads();
    unsigned woff = 0;
    #pragma unroll
    for (int w = 0; w < 16; w++) woff += (w < warp) ? wcnt[w] : 0u;
    unsigned myoff = woff + __popc(ball & ((1u << lane) - 1u));

    bool zero = (key < tau) || (eq && myoff < E);
    float t = zero ? 0.f : gc;

    float sum = t;
    #pragma unroll
    for (int o = 16; o; o >>= 1) sum += __shfl_xor_sync(0xffffffffu, sum, o);
    if (lane == 0) ssum[warp] = sum;
    __syncthreads();
    if (c == 0) {
        float tot = 0.f;
        #pragma unroll
        for (int w = 0; w < 16; w++) tot += ssum[w];
        ssum[16] = tot;
    }
    __syncthreads();
    out[b * COUT + c] = t * ((float)COUT / ssum[16]);
}

// ---------------------------------------------------------------------------
extern "C" void kernel_launch(void* const* d_in, const int* in_sizes, int n_in,
                              void* d_out, int out_size) {
    const float* x    = (const float*)d_in[0];
    const float* W    = (const float*)d_in[1];
    const float* bias = (const float*)d_in[2];
    float* out = (float*)d_out;

    cudaFuncSetAttribute(k1_absmean, cudaFuncAttributeMaxDynamicSharedMemorySize,
                         K1_SMEM);
    cudaFuncSetAttribute(k2_gate, cudaFuncAttributeMaxDynamicSharedMemorySize,
                         K2_SMEM_BYTES);

    k1_absmean<<<K1_BLOCKS, 256, K1_SMEM>>>(x);

    // k2 with Programmatic Dependent Launch (launches into k1's drain window)
    {
        cudaLaunchConfig_t cfg = {};
        cfg.gridDim  = dim3(16, 8);
        cfg.blockDim = dim3(512);
        cfg.dynamicSmemBytes = K2_SMEM_BYTES;
        cfg.stream = 0;
        cudaLaunchAttribute at[1];
        at[0].id = cudaLaunchAttributeProgrammaticStreamSerialization;
        at[0].val.programmaticStreamSerializationAllowed = 1;
        cfg.attrs = at;
        cfg.numAttrs = 1;
        cudaLaunchKernelEx(&cfg, k2_gate, W, bias);
    }

    // k3 with PDL: dispatch overlaps k2's tail.
    {
        cudaLaunchConfig_t cfg = {};
        cfg.gridDim  = dim3(B_);
        cfg.blockDim = dim3(512);
        cfg.dynamicSmemBytes = 0;
        cfg.stream = 0;
        cudaLaunchAttribute at[1];
        at[0].id = cudaLaunchAttributeProgrammaticStreamSerialization;
        at[0].val.programmaticStreamSerializationAllowed = 1;
        cfg.attrs = at;
        cfg.numAttrs = 1;
        cudaLaunchKernelEx(&cfg, k3_select, out);
    }
}